// round 11
// baseline (speedup 1.0000x reference)
#include <cuda_runtime.h>
#include <math.h>

// LabelAttention2: B=8, S=4096, L=64, DQ=DK=DV=1024, H=256
// Single persistent kernel, 444 blocks (148 SMs x 3) x 256 threads.
// scores[b,s] = (Q[b,s,:].w + c0)/16 ; w = Wq_w^T @ kcol,
// kcol = Wk_w @ ksum + L*Wk_b, ksum = sum_l K[l,:].
// Unnormalized softmax. P2: per-warp compacted-row score stream (prefetched
// indices, low regs). P3: per-warp (batch, half-row) context accumulator,
// ballot-compacted V loads. No block syncs inside streaming loops.

#define BATCH 8
#define SEQ   4096
#define NROWS (BATCH * SEQ)
#define DQDIM 1024
#define DVDIM 1024
#define LDIM  64
#define HDIM  256
#define NBLK  444
#define NTHR  256
#define NWARP (NBLK * 8)        // 3552
#define ZPAD  37
#define CSTR  (NWARP / 16)      // 222 warps per (batch,half) set

__device__ __align__(16) float g_ksum[DQDIM];
__device__ __align__(16) float g_w[DQDIM];
__device__ float g_c0;
__device__ __align__(16) float g_attn[NROWS];  // unnormalized exp(score)
__device__ float g_Zp[BATCH * ZPAD];           // padded Z partials
__device__ int   g_rows[NROWS];
__device__ int   g_nrows;

__device__ unsigned          g_barcnt = 0;
__device__ volatile unsigned g_bargen = 0;

__device__ __forceinline__ void gridbar() {
    __syncthreads();
    if (threadIdx.x == 0) {
        unsigned gen = g_bargen;
        __threadfence();
        if (atomicAdd(&g_barcnt, 1u) == NBLK - 1) {
            g_barcnt = 0;
            __threadfence();
            g_bargen = gen + 1;
        } else {
            while (g_bargen == gen) { }
        }
    }
    __syncthreads();
}

__global__ void __launch_bounds__(NTHR, 3) fused_kernel(
    const float* __restrict__ Q, const float* __restrict__ K,
    const float* __restrict__ V, const void* __restrict__ maskp,
    const float* __restrict__ Wq_w, const float* __restrict__ Wq_b,
    const float* __restrict__ Wk_w, const float* __restrict__ Wk_b,
    float* __restrict__ out, int write_attn)
{
    int b = blockIdx.x;
    int t = threadIdx.x;
    int lane = t & 31;
    int warp = t >> 5;

    __shared__ float sred[8];
    __shared__ float s_kcol;
    __shared__ __align__(16) float sw[DQDIM];
    __shared__ float zsum[BATCH];
    __shared__ float s_inv[BATCH];

    // ---------------- P0: ksum, zeros, out-context zero --------------------
    if (b < 4) {
        int dk = b * 256 + t;
        float s = 0.f;
#pragma unroll
        for (int l = 0; l < LDIM; l++) s += K[l * DQDIM + dk];
        g_ksum[dk] = s;
        g_w[dk] = 0.f;
    } else if (b == 4) {
        if (t == 0) g_c0 = 0.f;
        if (t == 1) g_nrows = 0;
    } else if (b == 5) {
        g_Zp[t] = 0.f;                       // 0..255
    } else if (b == 6) {
        if (t < BATCH * ZPAD - 256) g_Zp[256 + t] = 0.f;
    } else if (b >= 8 && b < 40) {
        out[(b - 8) * 256 + t] = 0.f;        // 32*256 = 8192 = B*DV
    }
    gridbar();

    // ---------------- P1: kcol[b] + rank-1 scatter into w; compaction ------
    if (b < HDIM) {
        const float4* wk4 = (const float4*)(Wk_w + (long)b * DQDIM);
        const float4* ks4 = (const float4*)g_ksum;
        float4 a = wk4[t];
        float4 k = __ldcg(&ks4[t]);
        float acc = a.x * k.x + a.y * k.y + a.z * k.z + a.w * k.w;
#pragma unroll
        for (int o = 16; o; o >>= 1) acc += __shfl_xor_sync(0xFFFFFFFFu, acc, o);
        if (lane == 0) sred[warp] = acc;
        __syncthreads();
        if (t == 0) {
            float s = 0.f;
#pragma unroll
            for (int i = 0; i < 8; i++) s += sred[i];
            s_kcol = s + (float)LDIM * Wk_b[b];
        }
        __syncthreads();
        float kc = s_kcol;
#pragma unroll
        for (int j = 0; j < 4; j++) {
            int dq = t + j * 256;
            atomicAdd(&g_w[dq], kc * Wq_w[(long)b * DQDIM + dq]);
        }
        if (t == 0) atomicAdd(&g_c0, kc * Wq_b[b]);
    }
    if (b < 32) {
        // mask dtype: int32 mask -> these words all 0/1; byte mask -> some
        // word >1 w.p. ~1-8^-256
        const unsigned* mw = (const unsigned*)maskp;
        int isbyte = __syncthreads_or(mw[b * 256 + t] > 1u);

        int row0 = b * 1024 + t * 4;
        unsigned mm[4];
        if (isbyte) {
            const unsigned char* mp = (const unsigned char*)maskp;
#pragma unroll
            for (int i = 0; i < 4; i++) mm[i] = mp[row0 + i];
        } else {
            const int* mp = (const int*)maskp;
#pragma unroll
            for (int i = 0; i < 4; i++) mm[i] = (unsigned)mp[row0 + i];
        }
        int keep[4];
        int nc = 0;
#pragma unroll
        for (int i = 0; i < 4; i++) {
            if (!mm[i]) keep[nc++] = row0 + i;
            else        g_attn[row0 + i] = 0.f;
        }
        int pos = nc;
#pragma unroll
        for (int o = 1; o < 32; o <<= 1) {
            int v = __shfl_up_sync(0xFFFFFFFFu, pos, o);
            if (lane >= o) pos += v;
        }
        int wtotal = __shfl_sync(0xFFFFFFFFu, pos, 31);
        pos -= nc;
        int base = 0;
        if (lane == 31) base = atomicAdd(&g_nrows, wtotal);
        base = __shfl_sync(0xFFFFFFFFu, base, 31);
        for (int i = 0; i < nc; i++) g_rows[base + pos + i] = keep[i];
    }
    gridbar();

    // ---------------- P2: scores (per-warp stride, prefetched index) -------
    {
        for (int i = t; i < DQDIM; i += 256) sw[i] = __ldcg(&g_w[i]);
        if (t < BATCH) zsum[t] = 0.f;
        __syncthreads();

        int   nr = __ldcg(&g_nrows);
        float c0 = __ldcg(&g_c0);
        int   gw = b * 8 + warp;            // 0..NWARP-1
        const float4* sw4 = (const float4*)sw;

        int i  = gw;
        int row = (i < nr) ? __ldcg(&g_rows[i]) : -1;
#pragma unroll 1
        while (row >= 0) {
            int inext = i + NWARP;
            int rownext = (inext < nr) ? __ldcg(&g_rows[inext]) : -1;

            const float4* q4 = (const float4*)(Q + (long)row * DQDIM);
            float4 q[8];
#pragma unroll
            for (int j = 0; j < 8; j++) q[j] = q4[lane + 32 * j];
            float a = 0.f;
#pragma unroll
            for (int j = 0; j < 8; j++) {
                float4 w = sw4[lane + 32 * j];
                a += q[j].x * w.x + q[j].y * w.y + q[j].z * w.z + q[j].w * w.w;
            }
#pragma unroll
            for (int o = 16; o; o >>= 1)
                a += __shfl_xor_sync(0xFFFFFFFFu, a, o);
            float e = __expf((a + c0) * 0.0625f);
            if (lane == 0) {
                g_attn[row] = e;
                atomicAdd(&zsum[row >> 12], e);
            }
            i = inext;
            row = rownext;
        }
        __syncthreads();
        if (t < BATCH && zsum[t] != 0.f)
            atomicAdd(&g_Zp[t * ZPAD + (b % ZPAD)], zsum[t]);
    }
    gridbar();

    // ---------------- P3: context (warp owns (batch, half-row)) ------------
    {
        if (t < BATCH) {
            float z = 0.f;
            for (int i = 0; i < ZPAD; i++) z += __ldcg(&g_Zp[t * ZPAD + i]);
            s_inv[t] = 1.f / z;
        }
        __syncthreads();

        if (write_attn && b < 128) {
            int row = b * 256 + t;
            out[BATCH * DVDIM + row] = __ldcg(&g_attn[row]) * s_inv[row >> 12];
        }

        int gw    = b * 8 + warp;
        int set   = gw & 15;
        int batch = set & 7;
        int half  = set >> 3;
        int s     = gw >> 4;                 // 0..CSTR-1
        float inv = s_inv[batch];
        int nmax  = (SEQ - s + CSTR - 1) / CSTR;   // rows for this warp

        const float4* vb = (const float4*)V;
        long vofs = (long)batch * SEQ * 256 + half * 128;

        float4 acc0 = make_float4(0.f, 0.f, 0.f, 0.f);
        float4 acc1 = acc0, acc2 = acc0, acc3 = acc0;

        // chunk 0 weights (lanes 0-7)
        float wv = (lane < 8 && lane < nmax)
                 ? __ldcg(&g_attn[batch * SEQ + s + CSTR * lane]) : 0.f;

#pragma unroll 1
        for (int k = 0; 8 * k < nmax; k++) {
            int nb = 8 * (k + 1);
            float wv_next = (lane < 8 && nb + lane < nmax)
                ? __ldcg(&g_attn[batch * SEQ + s + CSTR * (nb + lane)]) : 0.f;

            float wn = wv * inv;
            unsigned bits =
                __ballot_sync(0xFFFFFFFFu, (lane < 8) && (wn > 1e-9f)) & 0xFFu;
            while (bits) {
                int j1 = __ffs(bits) - 1; bits &= bits - 1;
                int j2 = -1;
                if (bits) { j2 = __ffs(bits) - 1; bits &= bits - 1; }
                float w1 = __shfl_sync(0xFFFFFFFFu, wn, j1);
                long  r1 = s + (long)CSTR * (8 * k + j1);
                const float4* v1 = vb + vofs + r1 * 256;
                float4 a0 = v1[lane], a1 = v1[32 + lane],
                       a2 = v1[64 + lane], a3 = v1[96 + lane];
                if (j2 >= 0) {
                    float w2 = __shfl_sync(0xFFFFFFFFu, wn, j2);
                    long  r2 = s + (long)CSTR * (8 * k + j2);
                    const float4* v2 = vb + vofs + r2 * 256;
                    float4 b0 = v2[lane], b1 = v2[32 + lane],
                           b2 = v2[64 + lane], b3 = v2[96 + lane];
                    acc0.x += w1 * a0.x + w2 * b0.x; acc0.y += w1 * a0.y + w2 * b0.y;
                    acc0.z += w1 * a0.z + w2 * b0.z; acc0.w += w1 * a0.w + w2 * b0.w;
                    acc1.x += w1 * a1.x + w2 * b1.x; acc1.y += w1 * a1.y + w2 * b1.y;
                    acc1.z += w1 * a1.z + w2 * b1.z; acc1.w += w1 * a1.w + w2 * b1.w;
                    acc2.x += w1 * a2.x + w2 * b2.x; acc2.y += w1 * a2.y + w2 * b2.y;
                    acc2.z += w1 * a2.z + w2 * b2.z; acc2.w += w1 * a2.w + w2 * b2.w;
                    acc3.x += w1 * a3.x + w2 * b3.x; acc3.y += w1 * a3.y + w2 * b3.y;
                    acc3.z += w1 * a3.z + w2 * b3.z; acc3.w += w1 * a3.w + w2 * b3.w;
                } else {
                    acc0.x += w1 * a0.x; acc0.y += w1 * a0.y;
                    acc0.z += w1 * a0.z; acc0.w += w1 * a0.w;
                    acc1.x += w1 * a1.x; acc1.y += w1 * a1.y;
                    acc1.z += w1 * a1.z; acc1.w += w1 * a1.w;
                    acc2.x += w1 * a2.x; acc2.y += w1 * a2.y;
                    acc2.z += w1 * a2.z; acc2.w += w1 * a2.w;
                    acc3.x += w1 * a3.x; acc3.y += w1 * a3.y;
                    acc3.z += w1 * a3.z; acc3.w += w1 * a3.w;
                }
            }
            wv = wv_next;
        }

        // flush: warp's 512-float half into out[batch]
        float* ob = out + (long)batch * DVDIM + half * 512;
        atomicAdd(ob + (0 * 32 + lane) * 4 + 0, acc0.x);
        atomicAdd(ob + (0 * 32 + lane) * 4 + 1, acc0.y);
        atomicAdd(ob + (0 * 32 + lane) * 4 + 2, acc0.z);
        atomicAdd(ob + (0 * 32 + lane) * 4 + 3, acc0.w);
        atomicAdd(ob + (1 * 32 + lane) * 4 + 0, acc1.x);
        atomicAdd(ob + (1 * 32 + lane) * 4 + 1, acc1.y);
        atomicAdd(ob + (1 * 32 + lane) * 4 + 2, acc1.z);
        atomicAdd(ob + (1 * 32 + lane) * 4 + 3, acc1.w);
        atomicAdd(ob + (2 * 32 + lane) * 4 + 0, acc2.x);
        atomicAdd(ob + (2 * 32 + lane) * 4 + 1, acc2.y);
        atomicAdd(ob + (2 * 32 + lane) * 4 + 2, acc2.z);
        atomicAdd(ob + (2 * 32 + lane) * 4 + 3, acc2.w);
        atomicAdd(ob + (3 * 32 + lane) * 4 + 0, acc3.x);
        atomicAdd(ob + (3 * 32 + lane) * 4 + 1, acc3.y);
        atomicAdd(ob + (3 * 32 + lane) * 4 + 2, acc3.z);
        atomicAdd(ob + (3 * 32 + lane) * 4 + 3, acc3.w);
    }
}

// ---------------------------------------------------------------------------
extern "C" void kernel_launch(void* const* d_in, const int* in_sizes, int n_in,
                              void* d_out, int out_size) {
    const float* Q    = (const float*)d_in[0];
    const float* K    = (const float*)d_in[1];
    const float* V    = (const float*)d_in[2];
    const void*  mask = d_in[3];
    const float* Wq_w = (const float*)d_in[4];
    const float* Wq_b = (const float*)d_in[5];
    const float* Wk_w = (const float*)d_in[6];
    const float* Wk_b = (const float*)d_in[7];
    float* out = (float*)d_out;

    int write_attn = (out_size >= BATCH * (DVDIM + SEQ)) ? 1 : 0;

    fused_kernel<<<NBLK, NTHR>>>(Q, K, V, mask, Wq_w, Wq_b, Wk_w, Wk_b,
                                 out, write_attn);
}

// round 12
// speedup vs baseline: 1.3810x; 1.3810x over previous
#include <cuda_runtime.h>
#include <math.h>

// LabelAttention2: B=8, S=4096, L=64, DQ=DK=DV=1024, H=256
// Single persistent kernel, 444 blocks (148 SMs x 3) x 256 threads.
// scores[b,s] = (Q[b,s,:].w + c0)/16 ; w = Wq_w^T @ kcol,
// kcol = Wk_w @ ksum + L*Wk_b, ksum = sum_l K[l,:].
// Unnormalized softmax. P2: per-warp compacted-row score stream (prefetched
// index, low regs, sync-free). P3: 64-row tiles, smem compaction, 8-wide
// branch-free V loads (the R7-proven structure), statically strided.

#define BATCH 8
#define SEQ   4096
#define NROWS (BATCH * SEQ)
#define DQDIM 1024
#define DVDIM 1024
#define LDIM  64
#define HDIM  256
#define NBLK  444
#define NTHR  256
#define NWARP (NBLK * 8)        // 3552
#define ZPAD  37
#define CTROWS 64
#define NCTILE (NROWS / CTROWS) // 512

__device__ __align__(16) float g_ksum[DQDIM];
__device__ __align__(16) float g_w[DQDIM];
__device__ float g_c0;
__device__ __align__(16) float g_attn[NROWS];  // unnormalized exp(score)
__device__ float g_Zp[BATCH * ZPAD];           // padded Z partials
__device__ int   g_rows[NROWS];
__device__ int   g_nrows;

__device__ unsigned          g_barcnt = 0;
__device__ volatile unsigned g_bargen = 0;

__device__ __forceinline__ void gridbar() {
    __syncthreads();
    if (threadIdx.x == 0) {
        unsigned gen = g_bargen;
        __threadfence();
        if (atomicAdd(&g_barcnt, 1u) == NBLK - 1) {
            g_barcnt = 0;
            __threadfence();
            g_bargen = gen + 1;
        } else {
            while (g_bargen == gen) { }
        }
    }
    __syncthreads();
}

__global__ void __launch_bounds__(NTHR, 3) fused_kernel(
    const float* __restrict__ Q, const float* __restrict__ K,
    const float* __restrict__ V, const void* __restrict__ maskp,
    const float* __restrict__ Wq_w, const float* __restrict__ Wq_b,
    const float* __restrict__ Wk_w, const float* __restrict__ Wk_b,
    float* __restrict__ out, int write_attn)
{
    int b = blockIdx.x;
    int t = threadIdx.x;
    int lane = t & 31;
    int warp = t >> 5;

    __shared__ float sred[8];
    __shared__ float s_kcol;
    __shared__ __align__(16) float sw[DQDIM];
    __shared__ float zsum[BATCH];
    __shared__ float s_inv[BATCH];
    __shared__ float wc[CTROWS + 8];
    __shared__ int   slist[CTROWS + 8];
    __shared__ int   scnt;

    // ---------------- P0: ksum, zeros, out-context zero --------------------
    if (b < 4) {
        int dk = b * 256 + t;
        float s = 0.f;
#pragma unroll
        for (int l = 0; l < LDIM; l++) s += K[l * DQDIM + dk];
        g_ksum[dk] = s;
        g_w[dk] = 0.f;
    } else if (b == 4) {
        if (t == 0) g_c0 = 0.f;
        if (t == 1) g_nrows = 0;
    } else if (b == 5) {
        g_Zp[t] = 0.f;                       // 0..255
    } else if (b == 6) {
        if (t < BATCH * ZPAD - 256) g_Zp[256 + t] = 0.f;
    } else if (b >= 8 && b < 40) {
        out[(b - 8) * 256 + t] = 0.f;        // 32*256 = 8192 = B*DV
    }
    gridbar();

    // ---------------- P1: kcol[b] + rank-1 scatter into w; compaction ------
    if (b < HDIM) {
        const float4* wk4 = (const float4*)(Wk_w + (long)b * DQDIM);
        const float4* ks4 = (const float4*)g_ksum;
        float4 a = wk4[t];
        float4 k = __ldcg(&ks4[t]);
        float acc = a.x * k.x + a.y * k.y + a.z * k.z + a.w * k.w;
#pragma unroll
        for (int o = 16; o; o >>= 1) acc += __shfl_xor_sync(0xFFFFFFFFu, acc, o);
        if (lane == 0) sred[warp] = acc;
        __syncthreads();
        if (t == 0) {
            float s = 0.f;
#pragma unroll
            for (int i = 0; i < 8; i++) s += sred[i];
            s_kcol = s + (float)LDIM * Wk_b[b];
        }
        __syncthreads();
        float kc = s_kcol;
#pragma unroll
        for (int j = 0; j < 4; j++) {
            int dq = t + j * 256;
            atomicAdd(&g_w[dq], kc * Wq_w[(long)b * DQDIM + dq]);
        }
        if (t == 0) atomicAdd(&g_c0, kc * Wq_b[b]);
    }
    if (b < 32) {
        // mask dtype: int32 mask -> these words all 0/1; byte mask -> some
        // word >1 w.p. ~1-8^-256
        const unsigned* mw = (const unsigned*)maskp;
        int isbyte = __syncthreads_or(mw[b * 256 + t] > 1u);

        int row0 = b * 1024 + t * 4;
        unsigned mm[4];
        if (isbyte) {
            const unsigned char* mp = (const unsigned char*)maskp;
#pragma unroll
            for (int i = 0; i < 4; i++) mm[i] = mp[row0 + i];
        } else {
            const int* mp = (const int*)maskp;
#pragma unroll
            for (int i = 0; i < 4; i++) mm[i] = (unsigned)mp[row0 + i];
        }
        int keep[4];
        int nc = 0;
#pragma unroll
        for (int i = 0; i < 4; i++) {
            if (!mm[i]) keep[nc++] = row0 + i;
            else        g_attn[row0 + i] = 0.f;
        }
        int pos = nc;
#pragma unroll
        for (int o = 1; o < 32; o <<= 1) {
            int v = __shfl_up_sync(0xFFFFFFFFu, pos, o);
            if (lane >= o) pos += v;
        }
        int wtotal = __shfl_sync(0xFFFFFFFFu, pos, 31);
        pos -= nc;
        int base = 0;
        if (lane == 31) base = atomicAdd(&g_nrows, wtotal);
        base = __shfl_sync(0xFFFFFFFFu, base, 31);
        for (int i = 0; i < nc; i++) g_rows[base + pos + i] = keep[i];
    }
    gridbar();

    // ---------------- P2: scores (per-warp stride, prefetched index) -------
    {
        for (int i = t; i < DQDIM; i += 256) sw[i] = __ldcg(&g_w[i]);
        if (t < BATCH) zsum[t] = 0.f;
        __syncthreads();

        int   nr = __ldcg(&g_nrows);
        float c0 = __ldcg(&g_c0);
        int   gw = b * 8 + warp;            // 0..NWARP-1
        const float4* sw4 = (const float4*)sw;

        int i  = gw;
        int row = (i < nr) ? __ldcg(&g_rows[i]) : -1;
#pragma unroll 1
        while (row >= 0) {
            int inext = i + NWARP;
            int rownext = (inext < nr) ? __ldcg(&g_rows[inext]) : -1;

            const float4* q4 = (const float4*)(Q + (long)row * DQDIM);
            float4 q[8];
#pragma unroll
            for (int j = 0; j < 8; j++) q[j] = q4[lane + 32 * j];
            float a = 0.f;
#pragma unroll
            for (int j = 0; j < 8; j++) {
                float4 w = sw4[lane + 32 * j];
                a += q[j].x * w.x + q[j].y * w.y + q[j].z * w.z + q[j].w * w.w;
            }
#pragma unroll
            for (int o = 16; o; o >>= 1)
                a += __shfl_xor_sync(0xFFFFFFFFu, a, o);
            float e = __expf((a + c0) * 0.0625f);
            if (lane == 0) {
                g_attn[row] = e;
                atomicAdd(&zsum[row >> 12], e);
            }
            i = inext;
            row = rownext;
        }
        __syncthreads();
        if (t < BATCH && zsum[t] != 0.f)
            atomicAdd(&g_Zp[t * ZPAD + (b % ZPAD)], zsum[t]);
    }
    gridbar();

    // ---------------- P3: context (64-row tiles, R7 structure) -------------
    {
        if (t < BATCH) {
            float z = 0.f;
            for (int i = 0; i < ZPAD; i++) z += __ldcg(&g_Zp[t * ZPAD + i]);
            s_inv[t] = 1.f / z;
        }
        __syncthreads();

#pragma unroll 1
        for (int tile = b; tile < NCTILE; tile += NBLK) {
            int rowbase = tile * CTROWS;
            int bb = rowbase >> 12;
            float inv = s_inv[bb];

            if (t == 0) scnt = 0;
            __syncthreads();

            if (t < CTROWS) {
                int row = rowbase + t;
                float w = __ldcg(&g_attn[row]) * inv;
                if (write_attn)
                    out[BATCH * DVDIM + row] = w;
                if (w > 1e-9f) {   // total mass loss <= 4e-6 << 1e-3 gate
                    int p = atomicAdd(&scnt, 1);
                    wc[p]    = w;
                    slist[p] = row;
                }
            }
            __syncthreads();
            int n = scnt;
            int npad = (n + 7) & ~7;
            if (t < npad - n) { wc[n + t] = 0.f; slist[n + t] = rowbase; }
            __syncthreads();

            float4 acc = make_float4(0.f, 0.f, 0.f, 0.f);
#pragma unroll 1
            for (int s = 0; s < npad; s += 8) {
#pragma unroll
                for (int i = 0; i < 8; i++) {
                    float w  = wc[s + i];
                    const float4* v4 =
                        (const float4*)(V + (long)slist[s + i] * DVDIM);
                    float4 v = v4[t];
                    acc.x += w * v.x; acc.y += w * v.y;
                    acc.z += w * v.z; acc.w += w * v.w;
                }
            }
            float* o = out + bb * DVDIM + t * 4;
            atomicAdd(o + 0, acc.x);
            atomicAdd(o + 1, acc.y);
            atomicAdd(o + 2, acc.z);
            atomicAdd(o + 3, acc.w);
            __syncthreads();   // protect smem reuse next tile
        }
    }
}

// ---------------------------------------------------------------------------
extern "C" void kernel_launch(void* const* d_in, const int* in_sizes, int n_in,
                              void* d_out, int out_size) {
    const float* Q    = (const float*)d_in[0];
    const float* K    = (const float*)d_in[1];
    const float* V    = (const float*)d_in[2];
    const void*  mask = d_in[3];
    const float* Wq_w = (const float*)d_in[4];
    const float* Wq_b = (const float*)d_in[5];
    const float* Wk_w = (const float*)d_in[6];
    const float* Wk_b = (const float*)d_in[7];
    float* out = (float*)d_out;

    int write_attn = (out_size >= BATCH * (DVDIM + SEQ)) ? 1 : 0;

    fused_kernel<<<NBLK, NTHR>>>(Q, K, V, mask, Wq_w, Wq_b, Wk_w, Wk_b,
                                 out, write_attn);
}

// round 13
// speedup vs baseline: 1.8111x; 1.3115x over previous
#include <cuda_runtime.h>
#include <math.h>

// LabelAttention2: B=8, S=4096, L=64, DQ=DK=DV=1024, H=256
// Single persistent kernel, 296 blocks (148 SMs x 2, exact) x 256 threads.
// scores[b,s] = (Q[b,s,:].w + c0)/16 ; w = Wq_w^T @ kcol,
// kcol = Wk_w @ ksum + L*Wk_b, ksum = sum_l K[l,:].
// Unnormalized softmax. P2: 2 rows/warp-iter, front-batched loads, NEXT
// indices prefetched. P3: exact per-block row ranges (batch-split), smem
// compaction, 16-wide branch-free V loads.

#define BATCH 8
#define SEQ   4096
#define NROWS (BATCH * SEQ)
#define DQDIM 1024
#define DVDIM 1024
#define LDIM  64
#define HDIM  256
#define NBLK  296
#define NTHR  256
#define NWARP (NBLK * 8)        // 2368

__device__ __align__(16) float g_ksum[DQDIM];
__device__ __align__(16) float g_w[DQDIM];
__device__ float g_c0;
__device__ __align__(16) float g_attn[NROWS];  // unnormalized exp(score)
__device__ float g_Z[BATCH];
__device__ int   g_rows[NROWS];
__device__ int   g_nrows;

__device__ unsigned          g_barcnt = 0;
__device__ volatile unsigned g_bargen = 0;

__device__ __forceinline__ void gridbar() {
    __syncthreads();
    if (threadIdx.x == 0) {
        unsigned gen = g_bargen;
        __threadfence();
        if (atomicAdd(&g_barcnt, 1u) == NBLK - 1) {
            g_barcnt = 0;
            __threadfence();
            g_bargen = gen + 1;
        } else {
            while (g_bargen == gen) { }
        }
    }
    __syncthreads();
}

__global__ void __launch_bounds__(NTHR, 2) fused_kernel(
    const float* __restrict__ Q, const float* __restrict__ K,
    const float* __restrict__ V, const void* __restrict__ maskp,
    const float* __restrict__ Wq_w, const float* __restrict__ Wq_b,
    const float* __restrict__ Wk_w, const float* __restrict__ Wk_b,
    float* __restrict__ out, int write_attn)
{
    int b = blockIdx.x;
    int t = threadIdx.x;
    int lane = t & 31;
    int warp = t >> 5;

    __shared__ float sred[8];
    __shared__ float s_kcol;
    __shared__ __align__(16) float sw[DQDIM];
    __shared__ float zsum[BATCH];
    __shared__ float s_inv[BATCH];
    __shared__ float wc[144];
    __shared__ int   slist[144];
    __shared__ int   scnt;

    // ---------------- P0: ksum, zeros, out-context zero --------------------
    if (b < 4) {
        int dk = b * 256 + t;
        float s = 0.f;
#pragma unroll
        for (int l = 0; l < LDIM; l++) s += K[l * DQDIM + dk];
        g_ksum[dk] = s;
        g_w[dk] = 0.f;
    } else if (b == 4) {
        if (t < BATCH) g_Z[t] = 0.f;
        if (t == 8)    g_c0 = 0.f;
        if (t == 9)    g_nrows = 0;
    } else if (b >= 8 && b < 40) {
        out[(b - 8) * 256 + t] = 0.f;        // 32*256 = 8192 = B*DV
    }
    gridbar();

    // ---------------- P1: kcol[b] + rank-1 scatter into w; compaction ------
    if (b < HDIM) {
        const float4* wk4 = (const float4*)(Wk_w + (long)b * DQDIM);
        const float4* ks4 = (const float4*)g_ksum;
        float4 a = wk4[t];
        float4 k = __ldcg(&ks4[t]);
        float acc = a.x * k.x + a.y * k.y + a.z * k.z + a.w * k.w;
#pragma unroll
        for (int o = 16; o; o >>= 1) acc += __shfl_xor_sync(0xFFFFFFFFu, acc, o);
        if (lane == 0) sred[warp] = acc;
        __syncthreads();
        if (t == 0) {
            float s = 0.f;
#pragma unroll
            for (int i = 0; i < 8; i++) s += sred[i];
            s_kcol = s + (float)LDIM * Wk_b[b];
        }
        __syncthreads();
        float kc = s_kcol;
#pragma unroll
        for (int j = 0; j < 4; j++) {
            int dq = t + j * 256;
            atomicAdd(&g_w[dq], kc * Wq_w[(long)b * DQDIM + dq]);
        }
        if (t == 0) atomicAdd(&g_c0, kc * Wq_b[b]);
    }
    if (b < 32) {
        // mask dtype detect: int32 mask -> words all 0/1
        const unsigned* mw = (const unsigned*)maskp;
        int isbyte = __syncthreads_or(mw[b * 256 + t] > 1u);

        int row0 = b * 1024 + t * 4;
        unsigned mm[4];
        if (isbyte) {
            const unsigned char* mp = (const unsigned char*)maskp;
#pragma unroll
            for (int i = 0; i < 4; i++) mm[i] = mp[row0 + i];
        } else {
            const int* mp = (const int*)maskp;
#pragma unroll
            for (int i = 0; i < 4; i++) mm[i] = (unsigned)mp[row0 + i];
        }
        int keep[4];
        int nc = 0;
#pragma unroll
        for (int i = 0; i < 4; i++) {
            if (!mm[i]) keep[nc++] = row0 + i;
            else        g_attn[row0 + i] = 0.f;
        }
        int pos = nc;
#pragma unroll
        for (int o = 1; o < 32; o <<= 1) {
            int v = __shfl_up_sync(0xFFFFFFFFu, pos, o);
            if (lane >= o) pos += v;
        }
        int wtotal = __shfl_sync(0xFFFFFFFFu, pos, 31);
        pos -= nc;
        int base = 0;
        if (lane == 31) base = atomicAdd(&g_nrows, wtotal);
        base = __shfl_sync(0xFFFFFFFFu, base, 31);
        for (int i = 0; i < nc; i++) g_rows[base + pos + i] = keep[i];
    }
    gridbar();

    // ---------------- P2: scores, 2 rows/iter, prefetched indices ----------
    {
        for (int i = t; i < DQDIM; i += 256) sw[i] = __ldcg(&g_w[i]);
        if (t < BATCH) zsum[t] = 0.f;
        __syncthreads();

        int   nr = __ldcg(&g_nrows);
        float c0 = __ldcg(&g_c0);
        const float4* sw4 = (const float4*)sw;

        int u    = b * 8 + warp;             // unit = 2 rows
        int iA   = 2 * u;
        int rowA = (iA     < nr) ? __ldcg(&g_rows[iA])     : -1;
        int rowB = (iA + 1 < nr) ? __ldcg(&g_rows[iA + 1]) : -1;

#pragma unroll 1
        while (rowA >= 0) {
            int un = u + NWARP;
            int jA = 2 * un;
            int nxtA = (jA     < nr) ? __ldcg(&g_rows[jA])     : -1;
            int nxtB = (jA + 1 < nr) ? __ldcg(&g_rows[jA + 1]) : -1;

            if (rowB >= 0) {
                const float4* qa4 = (const float4*)(Q + (long)rowA * DQDIM);
                const float4* qb4 = (const float4*)(Q + (long)rowB * DQDIM);
                float4 qa[8], qb[8];
#pragma unroll
                for (int j = 0; j < 8; j++) qa[j] = qa4[lane + 32 * j];
#pragma unroll
                for (int j = 0; j < 8; j++) qb[j] = qb4[lane + 32 * j];
                float a = 0.f, bb = 0.f;
#pragma unroll
                for (int j = 0; j < 8; j++) {
                    float4 w = sw4[lane + 32 * j];
                    a  += qa[j].x * w.x + qa[j].y * w.y + qa[j].z * w.z + qa[j].w * w.w;
                    bb += qb[j].x * w.x + qb[j].y * w.y + qb[j].z * w.z + qb[j].w * w.w;
                }
#pragma unroll
                for (int o = 16; o; o >>= 1) {
                    a  += __shfl_xor_sync(0xFFFFFFFFu, a, o);
                    bb += __shfl_xor_sync(0xFFFFFFFFu, bb, o);
                }
                if (lane == 0) {
                    float ea = __expf((a + c0) * 0.0625f);
                    float eb = __expf((bb + c0) * 0.0625f);
                    g_attn[rowA] = ea;
                    g_attn[rowB] = eb;
                    atomicAdd(&zsum[rowA >> 12], ea);
                    atomicAdd(&zsum[rowB >> 12], eb);
                }
            } else {   // tail: single row (at most once per warp)
                const float4* qa4 = (const float4*)(Q + (long)rowA * DQDIM);
                float a = 0.f;
#pragma unroll
                for (int j = 0; j < 8; j++) {
                    float4 q = qa4[lane + 32 * j];
                    float4 w = sw4[lane + 32 * j];
                    a += q.x * w.x + q.y * w.y + q.z * w.z + q.w * w.w;
                }
#pragma unroll
                for (int o = 16; o; o >>= 1)
                    a += __shfl_xor_sync(0xFFFFFFFFu, a, o);
                if (lane == 0) {
                    float ea = __expf((a + c0) * 0.0625f);
                    g_attn[rowA] = ea;
                    atomicAdd(&zsum[rowA >> 12], ea);
                }
            }
            u = un;
            rowA = nxtA;
            rowB = nxtB;
        }
        __syncthreads();
        if (t < BATCH && zsum[t] != 0.f) atomicAdd(&g_Z[t], zsum[t]);
    }
    gridbar();

    // ---------------- P3: context, exact row-ranges, 16-wide loads ---------
    {
        if (t < BATCH) s_inv[t] = 1.f / __ldcg(&g_Z[t]);
        __syncthreads();

        int rstart = (int)((long)b       * NROWS / NBLK);
        int rend   = (int)((long)(b + 1) * NROWS / NBLK);

#pragma unroll 1
        while (rstart < rend) {
            int bb     = rstart >> 12;
            int segend = min(rend, (bb + 1) << 12);   // batch-boundary split
            float inv  = s_inv[bb];
            float4 acc = make_float4(0.f, 0.f, 0.f, 0.f);

            int c0 = rstart;
#pragma unroll 1
            while (c0 < segend) {
                int cn = min(segend - c0, 128);
                if (t == 0) scnt = 0;
                __syncthreads();
                if (t < cn) {
                    int row = c0 + t;
                    float w = __ldcg(&g_attn[row]) * inv;
                    if (write_attn)
                        out[BATCH * DVDIM + row] = w;
                    if (w > 1e-9f) {   // mass loss <= 4e-6 << 1e-3 gate
                        int p = atomicAdd(&scnt, 1);
                        wc[p]    = w;
                        slist[p] = row;
                    }
                }
                __syncthreads();
                int n = scnt;
                int npad = (n + 15) & ~15;
                if (t < npad - n) { wc[n + t] = 0.f; slist[n + t] = c0; }
                __syncthreads();

#pragma unroll 1
                for (int s = 0; s < npad; s += 16) {
#pragma unroll
                    for (int i = 0; i < 16; i++) {
                        float w  = wc[s + i];
                        const float4* v4 =
                            (const float4*)(V + (long)slist[s + i] * DVDIM);
                        float4 v = v4[t];
                        acc.x += w * v.x; acc.y += w * v.y;
                        acc.z += w * v.z; acc.w += w * v.w;
                    }
                }
                c0 += cn;
            }
            float* o = out + bb * DVDIM + t * 4;
            atomicAdd(o + 0, acc.x);
            atomicAdd(o + 1, acc.y);
            atomicAdd(o + 2, acc.z);
            atomicAdd(o + 3, acc.w);
            rstart = segend;
        }
    }
}

// ---------------------------------------------------------------------------
extern "C" void kernel_launch(void* const* d_in, const int* in_sizes, int n_in,
                              void* d_out, int out_size) {
    const float* Q    = (const float*)d_in[0];
    const float* K    = (const float*)d_in[1];
    const float* V    = (const float*)d_in[2];
    const void*  mask = d_in[3];
    const float* Wq_w = (const float*)d_in[4];
    const float* Wq_b = (const float*)d_in[5];
    const float* Wk_w = (const float*)d_in[6];
    const float* Wk_b = (const float*)d_in[7];
    float* out = (float*)d_out;

    int write_attn = (out_size >= BATCH * (DVDIM + SEQ)) ? 1 : 0;

    fused_kernel<<<NBLK, NTHR>>>(Q, K, V, mask, Wq_w, Wq_b, Wk_w, Wk_b,
                                 out, write_attn);
}